// round 3
// baseline (speedup 1.0000x reference)
#include <cuda_runtime.h>
#include <cuda_bf16.h>
#include <math.h>

#define N        4096
#define T        4096
#define WASH     200
#define NBLK     128
#define TPB      512                 // 16 warps -> 4 per SMSP (latency hiding)
#define NWARP    (TPB / 32)
#define RPC      (N / NBLK)          // 32 rows per CTA
#define RPW      (RPC / NWARP)       // 2 rows per warp
#define L_CAP    1472                // per-CTA per-lane ELL word capacity
#define ELL_CAP  6291456             // global ELL words (mean ~5.06M)

// ---------------- device globals (no allocations allowed) ----------------
__device__ int      g_wpad[N];        // per-row padded (mult of 4) per-lane width
__device__ int      g_off[N + 1];     // exclusive prefix of g_wpad (per-lane units)
__device__ unsigned g_ell[ELL_CAP];   // packed (val & ~127) | j words, interleaved-4
__device__ float    g_x[2][N];
__device__ float    g_wv[N];          // wv[mask[i]] = w_out[i]
__device__ unsigned g_flag[NBLK];     // per-CTA step-publication flags

// ---- prep 1: per-row, per-bank widths (1 warp per row) -------------------
__global__ void k_width(const float* __restrict__ w) {
    int r    = blockIdx.x * 8 + (threadIdx.x >> 5);
    int lane = threadIdx.x & 31;
    if (r >= N) return;
    const float* row = w + (size_t)r * N;
    int cnt = 0;
    #pragma unroll 8
    for (int k = 0; k < N / 32; k++) cnt += (row[k * 32 + lane] != 0.0f);
    for (int o = 16; o; o >>= 1) {
        int v = __shfl_xor_sync(~0u, cnt, o);
        cnt = v > cnt ? v : cnt;
    }
    if (lane == 0) g_wpad[r] = (cnt + 3) & ~3;   // pad to multiple of 4
}

// ---- prep 2: exclusive prefix scan of g_wpad (1 block) -------------------
__global__ void k_scan() {
    __shared__ int sc[1024];
    int i = threadIdx.x;
    int a0 = g_wpad[4 * i + 0];
    int a1 = g_wpad[4 * i + 1];
    int a2 = g_wpad[4 * i + 2];
    int a3 = g_wpad[4 * i + 3];
    int s  = a0 + a1 + a2 + a3;
    sc[i] = s;
    __syncthreads();
    for (int d = 1; d < 1024; d <<= 1) {
        int v   = sc[i];
        int add = (i >= d) ? sc[i - d] : 0;
        __syncthreads();
        sc[i] = v + add;
        __syncthreads();
    }
    int excl = sc[i] - s;
    g_off[4 * i + 0] = excl;
    g_off[4 * i + 1] = excl + a0;
    g_off[4 * i + 2] = excl + a0 + a1;
    g_off[4 * i + 3] = excl + a0 + a1 + a2;
    if (i == 1023) g_off[N] = sc[1023];
}

// ---- prep 3: fill bank-sliced ELL with packed words (1 warp per row) -----
// Element (i, lane) of a row with base b lives at word
//   b*32 + (i>>2)*128 + lane*4 + (i&3).
// Packed word = (round_to_7(bits(val))) | j, where col = 32*j + lane.
__global__ void k_fillell(const float* __restrict__ w) {
    int r    = blockIdx.x * 8 + (threadIdx.x >> 5);
    int lane = threadIdx.x & 31;
    if (r >= N) return;
    const float* row = w + (size_t)r * N;
    int b   = g_off[r];
    int wid = g_off[r + 1] - b;
    unsigned* base = g_ell + (size_t)b * 32;
    int i = 0;
    for (int k = 0; k < N / 32; k++) {
        float v = row[k * 32 + lane];
        if (v != 0.0f) {
            unsigned bits = (__float_as_uint(v) + 64u) & ~127u;
            base[(i >> 2) * 128 + lane * 4 + (i & 3)] = bits | (unsigned)k;
            i++;
        }
    }
    for (; i < wid; i++)
        base[(i >> 2) * 128 + lane * 4 + (i & 3)] = 0u;   // padding: 0 * sx[lane]
}

// ---- prep 4: wv scatter, zero output, reset flags ------------------------
__global__ void k_prep(const float* __restrict__ w_out,
                       const int* __restrict__ mask,
                       float* __restrict__ out, int out_n) {
    int i = blockIdx.x * blockDim.x + threadIdx.x;
    if (i < N)     g_wv[mask[i]] = w_out[i];
    if (i < out_n) out[i] = 0.0f;
    if (i < NBLK)  g_flag[i] = 0u;
}

// ---------------- main persistent ESN kernel -----------------------------
__global__ void __launch_bounds__(TPB, 1)
k_esn(const float* __restrict__ u, const float* __restrict__ w_in,
      float* __restrict__ out) {
    extern __shared__ unsigned char smem_raw[];
    unsigned* sell = (unsigned*)smem_raw;                 // L_CAP*32 words
    float*    sx   = (float*)(sell + L_CAP * 32);         // N
    int*      lrp  = (int*)(sx + N);                      // RPC+1 (per-lane units)
    float*    wsum = (float*)(lrp + RPC + 1);             // NWARP

    const int c    = blockIdx.x;
    const int tid  = threadIdx.x;
    const int wid  = tid >> 5;
    const int lane = tid & 31;
    const int row0 = c * RPC;

    const int seg_beg = g_off[row0];
    int seg_pl = g_off[row0 + RPC] - seg_beg;
    if (seg_pl > L_CAP) seg_pl = L_CAP;

    for (int r = tid; r <= RPC; r += TPB) {
        int v = g_off[row0 + r] - seg_beg;
        lrp[r] = v > L_CAP ? L_CAP : v;
    }
    {   // copy ELL segment (16B-aligned: offsets are multiples of 4 per-lane units)
        const uint4* src = (const uint4*)(g_ell + (size_t)seg_beg * 32);
        uint4*       dst = (uint4*)sell;
        int nvec = seg_pl * 8;
        for (int k = tid; k < nvec; k += TPB) dst[k] = src[k];
    }
    for (int j = tid; j < N; j += TPB) sx[j] = 0.0f;
    __syncthreads();

    // hoist per-warp row metadata into registers
    int   kb[RPW], kw[RPW];
    float winr[RPW], wvr[RPW];
    #pragma unroll
    for (int rr = 0; rr < RPW; rr++) {
        int lr = wid * RPW + rr;
        kb[rr] = lrp[lr];
        kw[rr] = lrp[lr + 1] - lrp[lr];
        int gr = row0 + lr;
        winr[rr] = w_in[gr];
        wvr[rr]  = g_wv[gr];
    }

    for (int t = 0; t < T; ++t) {
        const float ut = __ldg(&u[t]);
        float* xout = g_x[t & 1];
        float xv[RPW];
        float partial = 0.0f;
        #pragma unroll
        for (int rr = 0; rr < RPW; rr++) {
            const uint4* p = (const uint4*)(sell + kb[rr] * 32 + lane * 4);
            float s = 0.0f;
            #pragma unroll 2
            for (int i = 0; i < kw[rr]; i += 4, p += 32) {
                uint4 q = *p;
                s += __uint_as_float(q.x & 0xFFFFFF80u) * sx[((q.x & 127u) << 5) + lane];
                s += __uint_as_float(q.y & 0xFFFFFF80u) * sx[((q.y & 127u) << 5) + lane];
                s += __uint_as_float(q.z & 0xFFFFFF80u) * sx[((q.z & 127u) << 5) + lane];
                s += __uint_as_float(q.w & 0xFFFFFF80u) * sx[((q.w & 127u) << 5) + lane];
            }
            for (int o = 16; o; o >>= 1) s += __shfl_xor_sync(~0u, s, o);
            if (lane == 0) {
                xv[rr] = tanhf(winr[rr] * ut + s);
                partial += wvr[rr] * xv[rr];
            }
        }
        if (lane == 0) {
            float2 st2; st2.x = xv[0]; st2.y = xv[1];
            __stcg((float2*)&xout[row0 + wid * RPW], st2);
            wsum[wid] = partial;
        }
        __syncthreads();   // all x writes + wsum done

        if (tid == 0) {
            // publish this CTA's chunk (cumulative release via the barrier above)
            asm volatile("st.release.gpu.global.u32 [%0], %1;"
                         :: "l"(&g_flag[c]), "r"((unsigned)(t + 1)) : "memory");
            if (t >= WASH) {     // off-critical-path output reduction
                float ys = 0.0f;
                #pragma unroll
                for (int w = 0; w < NWARP; w++) ys += wsum[w];
                atomicAdd(&out[t - WASH], ys);
            }
        }

        // fused poll + chunk reload: thread tid<128 owns CTA tid's 32-float chunk;
        // early chunks stream in while straggler CTAs still compute.
        if (tid < NBLK && t + 1 < T) {
            const unsigned tgt = (unsigned)(t + 1);
            unsigned v;
            do {
                asm volatile("ld.acquire.gpu.global.u32 %0, [%1];"
                             : "=r"(v) : "l"(&g_flag[tid]) : "memory");
            } while (v < tgt);
            const float4* src = (const float4*)(xout + (tid << 5));
            float4*       dst = (float4*)(sx + (tid << 5));
            float4 r0 = __ldcg(src + 0), r1 = __ldcg(src + 1);
            float4 r2 = __ldcg(src + 2), r3 = __ldcg(src + 3);
            float4 r4 = __ldcg(src + 4), r5 = __ldcg(src + 5);
            float4 r6 = __ldcg(src + 6), r7 = __ldcg(src + 7);
            dst[0] = r0; dst[1] = r1; dst[2] = r2; dst[3] = r3;
            dst[4] = r4; dst[5] = r5; dst[6] = r6; dst[7] = r7;
        }
        __syncthreads();
    }
}

// ---------------- launch ---------------------------------------------------
extern "C" void kernel_launch(void* const* d_in, const int* in_sizes, int n_in,
                              void* d_out, int out_size) {
    const float* u     = (const float*)d_in[0];
    const float* w_res = (const float*)d_in[1];
    const float* w_in  = (const float*)d_in[2];
    const float* w_out = (const float*)d_in[3];
    const int*   mask  = (const int*)d_in[4];
    float*       out   = (float*)d_out;

    const int smem_main = L_CAP * 32 * 4 + N * 4 + (RPC + 1) * 4 + NWARP * 4;
    cudaFuncSetAttribute(k_esn, cudaFuncAttributeMaxDynamicSharedMemorySize, smem_main);

    const int rows_grid = (N + 7) / 8;   // 1 warp per row, 8 warps per block
    k_width<<<rows_grid, 256>>>(w_res);
    k_scan<<<1, 1024>>>();
    k_fillell<<<rows_grid, 256>>>(w_res);
    k_prep<<<(N + 255) / 256, 256>>>(w_out, mask, out, out_size);
    k_esn<<<NBLK, TPB, smem_main>>>(u, w_in, out);
}

// round 4
// speedup vs baseline: 2.6753x; 2.6753x over previous
#include <cuda_runtime.h>
#include <cuda_bf16.h>
#include <math.h>

#define N        4096
#define T        4096
#define WASH     200
#define NBLK     128
#define TPB      256
#define RPC      (N / NBLK)          // 32 rows per CTA
#define RPW      (RPC / 8)           // 4 rows per warp
#define L_CAP    1472                // per-CTA per-lane ELL word capacity
#define ELL_CAP  6291456             // global ELL words (mean ~5.06M)

// ---------------- device globals (no allocations allowed) ----------------
__device__ int      g_wpad[N];        // per-row padded (mult of 4) per-lane width
__device__ int      g_off[N + 1];     // exclusive prefix of g_wpad (per-lane units)
__device__ unsigned g_ell[ELL_CAP];   // packed (val & ~127) | j words, interleaved-4
__device__ float    g_x[2][N];
__device__ float    g_wv[N];          // wv[mask[i]] = w_out[i]
__device__ unsigned g_bar;            // monotonic barrier counter (reset each launch)

// ---- prep 1: per-row, per-bank widths (1 warp per row) -------------------
__global__ void k_width(const float* __restrict__ w) {
    int r    = blockIdx.x * 8 + (threadIdx.x >> 5);
    int lane = threadIdx.x & 31;
    if (r >= N) return;
    const float* row = w + (size_t)r * N;
    int cnt = 0;
    #pragma unroll 8
    for (int k = 0; k < N / 32; k++) cnt += (row[k * 32 + lane] != 0.0f);
    for (int o = 16; o; o >>= 1) {
        int v = __shfl_xor_sync(~0u, cnt, o);
        cnt = v > cnt ? v : cnt;
    }
    if (lane == 0) g_wpad[r] = (cnt + 3) & ~3;   // pad to multiple of 4
}

// ---- prep 2: exclusive prefix scan of g_wpad (1 block) -------------------
__global__ void k_scan() {
    __shared__ int sc[1024];
    int i = threadIdx.x;
    int a0 = g_wpad[4 * i + 0];
    int a1 = g_wpad[4 * i + 1];
    int a2 = g_wpad[4 * i + 2];
    int a3 = g_wpad[4 * i + 3];
    int s  = a0 + a1 + a2 + a3;
    sc[i] = s;
    __syncthreads();
    for (int d = 1; d < 1024; d <<= 1) {
        int v   = sc[i];
        int add = (i >= d) ? sc[i - d] : 0;
        __syncthreads();
        sc[i] = v + add;
        __syncthreads();
    }
    int excl = sc[i] - s;
    g_off[4 * i + 0] = excl;
    g_off[4 * i + 1] = excl + a0;
    g_off[4 * i + 2] = excl + a0 + a1;
    g_off[4 * i + 3] = excl + a0 + a1 + a2;
    if (i == 1023) g_off[N] = sc[1023];
}

// ---- prep 3: fill bank-sliced ELL with packed words (1 warp per row) -----
// Element (i, lane) of a row with base b lives at word
//   b*32 + (i>>2)*128 + lane*4 + (i&3).
// Packed word = (round_to_7(bits(val))) | j, where col = 32*j + lane.
__global__ void k_fillell(const float* __restrict__ w) {
    int r    = blockIdx.x * 8 + (threadIdx.x >> 5);
    int lane = threadIdx.x & 31;
    if (r >= N) return;
    const float* row = w + (size_t)r * N;
    int b   = g_off[r];
    int wid = g_off[r + 1] - b;
    unsigned* base = g_ell + (size_t)b * 32;
    int i = 0;
    for (int k = 0; k < N / 32; k++) {
        float v = row[k * 32 + lane];
        if (v != 0.0f) {
            unsigned bits = (__float_as_uint(v) + 64u) & ~127u;
            base[(i >> 2) * 128 + lane * 4 + (i & 3)] = bits | (unsigned)k;
            i++;
        }
    }
    for (; i < wid; i++)
        base[(i >> 2) * 128 + lane * 4 + (i & 3)] = 0u;   // padding: 0 * sx[lane]
}

// ---- prep 4: wv scatter, zero output, reset barrier ----------------------
__global__ void k_prep(const float* __restrict__ w_out,
                       const int* __restrict__ mask,
                       float* __restrict__ out, int out_n) {
    int i = blockIdx.x * blockDim.x + threadIdx.x;
    if (i < N)     g_wv[mask[i]] = w_out[i];
    if (i < out_n) out[i] = 0.0f;
    if (i == 0)    g_bar = 0u;
}

// ---------------- main persistent ESN kernel -----------------------------
__global__ void __launch_bounds__(TPB, 1)
k_esn(const float* __restrict__ u, const float* __restrict__ w_in,
      float* __restrict__ out) {
    extern __shared__ unsigned char smem_raw[];
    unsigned* sell = (unsigned*)smem_raw;                 // L_CAP*32 words
    float*    sx   = (float*)(sell + L_CAP * 32);         // N
    int*      lrp  = (int*)(sx + N);                      // RPC+1 (per-lane units)
    float*    wsum = (float*)(lrp + RPC + 1);             // 8

    const int c    = blockIdx.x;
    const int tid  = threadIdx.x;
    const int wid  = tid >> 5;
    const int lane = tid & 31;
    const int row0 = c * RPC;

    const int seg_beg = g_off[row0];
    int seg_pl = g_off[row0 + RPC] - seg_beg;
    if (seg_pl > L_CAP) seg_pl = L_CAP;

    for (int r = tid; r <= RPC; r += TPB) {
        int v = g_off[row0 + r] - seg_beg;
        lrp[r] = v > L_CAP ? L_CAP : v;
    }
    {   // copy ELL segment (16B-aligned: offsets are multiples of 4 per-lane units)
        const uint4* src = (const uint4*)(g_ell + (size_t)seg_beg * 32);
        uint4*       dst = (uint4*)sell;
        int nvec = seg_pl * 8;
        for (int k = tid; k < nvec; k += TPB) dst[k] = src[k];
    }
    for (int j = tid; j < N; j += TPB) sx[j] = 0.0f;
    __syncthreads();

    // hoist per-warp row metadata into registers
    int   kb[RPW], kw[RPW];
    float winr[RPW], wvr[RPW];
    int   kmax = 0;
    #pragma unroll
    for (int rr = 0; rr < RPW; rr++) {
        int lr = wid * RPW + rr;
        kb[rr] = lrp[lr];
        kw[rr] = lrp[lr + 1] - lrp[lr];
        if (kw[rr] > kmax) kmax = kw[rr];
        int gr = row0 + lr;
        winr[rr] = w_in[gr];
        wvr[rr]  = g_wv[gr];
    }

    for (int t = 0; t < T; ++t) {
        const float ut = __ldg(&u[t]);
        float* xout = g_x[t & 1];
        float partial = 0.0f;

        // interleaved 4-row inner loop: 4 independent dep chains per warp
        const uint4* p[RPW];
        float s[RPW];
        #pragma unroll
        for (int rr = 0; rr < RPW; rr++) {
            p[rr] = (const uint4*)(sell + kb[rr] * 32 + lane * 4);
            s[rr] = 0.0f;
        }
        for (int i = 0; i < kmax; i += 4) {
            uint4 q[RPW];
            #pragma unroll
            for (int rr = 0; rr < RPW; rr++)
                if (i < kw[rr]) q[rr] = *p[rr];          // warp-uniform predicate
            #pragma unroll
            for (int rr = 0; rr < RPW; rr++)
                if (i < kw[rr]) {
                    s[rr] += __uint_as_float(q[rr].x & 0xFFFFFF80u) * sx[((q[rr].x & 127u) << 5) + lane];
                    s[rr] += __uint_as_float(q[rr].y & 0xFFFFFF80u) * sx[((q[rr].y & 127u) << 5) + lane];
                    s[rr] += __uint_as_float(q[rr].z & 0xFFFFFF80u) * sx[((q[rr].z & 127u) << 5) + lane];
                    s[rr] += __uint_as_float(q[rr].w & 0xFFFFFF80u) * sx[((q[rr].w & 127u) << 5) + lane];
                    p[rr] += 32;
                }
        }
        #pragma unroll
        for (int rr = 0; rr < RPW; rr++) {
            float v = s[rr];
            for (int o = 16; o; o >>= 1) v += __shfl_xor_sync(~0u, v, o);
            if (lane == 0) {
                float xv = tanhf(winr[rr] * ut + v);
                int gr = row0 + wid * RPW + rr;
                __stcg(&xout[gr], xv);
                partial += wvr[rr] * xv;
            }
        }
        if (lane == 0) wsum[wid] = partial;
        __syncthreads();   // orders the stcg x-writes before tid0's release below

        if (tid == 0) {
            // release-arrive publishes this CTA's x writes (cumulative release)
            asm volatile("red.release.gpu.global.add.u32 [%0], %1;"
                         :: "l"(&g_bar), "r"(1u) : "memory");
            if (t >= WASH) {          // off-critical-path, overlaps propagation
                float ys = 0.0f;
                #pragma unroll
                for (int w = 0; w < 8; w++) ys += wsum[w];
                atomicAdd(&out[t - WASH], ys);
            }
            unsigned target = (unsigned)(t + 1) * NBLK;
            unsigned v;
            do {
                asm volatile("ld.acquire.gpu.global.u32 %0, [%1];"
                             : "=r"(v) : "l"(&g_bar) : "memory");
            } while (v < target);
        }
        __syncthreads();

        if (t + 1 < T) {
            const float4* xs4 = (const float4*)xout;
            float4*       sx4 = (float4*)sx;
            #pragma unroll
            for (int j = 0; j < 4; j++) {
                int idx = tid + j * TPB;                 // 1024 float4s total
                sx4[idx] = __ldcg(&xs4[idx]);
            }
        }
    }
}

// ---------------- launch ---------------------------------------------------
extern "C" void kernel_launch(void* const* d_in, const int* in_sizes, int n_in,
                              void* d_out, int out_size) {
    const float* u     = (const float*)d_in[0];
    const float* w_res = (const float*)d_in[1];
    const float* w_in  = (const float*)d_in[2];
    const float* w_out = (const float*)d_in[3];
    const int*   mask  = (const int*)d_in[4];
    float*       out   = (float*)d_out;

    const int smem_main = L_CAP * 32 * 4 + N * 4 + (RPC + 1) * 4 + 8 * 4;
    cudaFuncSetAttribute(k_esn, cudaFuncAttributeMaxDynamicSharedMemorySize, smem_main);

    const int rows_grid = (N + 7) / 8;   // 1 warp per row, 8 warps per block
    k_width<<<rows_grid, 256>>>(w_res);
    k_scan<<<1, 1024>>>();
    k_fillell<<<rows_grid, 256>>>(w_res);
    k_prep<<<(N + 255) / 256, 256>>>(w_out, mask, out, out_size);
    k_esn<<<NBLK, TPB, smem_main>>>(u, w_in, out);
}

// round 5
// speedup vs baseline: 3.6085x; 1.3488x over previous
#include <cuda_runtime.h>
#include <cuda_bf16.h>
#include <math.h>

#define N        4096
#define T        4096
#define WASH     200
#define NBLK     128
#define TPB      256
#define RPC      (N / NBLK)          // 32 rows per CTA
#define RPW      (RPC / 8)           // 4 rows per warp (one warp-group shares width)
#define L_CAP    1472                // per-CTA per-lane ELL word capacity
#define ELL_CAP  6291456             // global ELL words

// ---------------- device globals (no allocations allowed) ----------------
__device__ int      g_cnt[N];         // per-row raw max-lane count
__device__ int      g_wpad[N];        // per-row width, warp-group-shared, mult of 4
__device__ int      g_off[N + 1];     // exclusive prefix of g_wpad (per-lane units)
__device__ unsigned g_ell[ELL_CAP];   // packed (val & ~127) | j words, interleaved-4
__device__ float    g_x[2][N];
__device__ float    g_wv[N];          // wv[mask[i]] = w_out[i]
__device__ unsigned g_bar;            // monotonic barrier counter (reset each launch)

// ---- prep 1: per-row max per-lane nonzero count (1 warp per row) ---------
__global__ void k_width(const float* __restrict__ w) {
    int r    = blockIdx.x * 8 + (threadIdx.x >> 5);
    int lane = threadIdx.x & 31;
    if (r >= N) return;
    const float* row = w + (size_t)r * N;
    int cnt = 0;
    #pragma unroll 8
    for (int k = 0; k < N / 32; k++) cnt += (row[k * 32 + lane] != 0.0f);
    for (int o = 16; o; o >>= 1) {
        int v = __shfl_xor_sync(~0u, cnt, o);
        cnt = v > cnt ? v : cnt;
    }
    if (lane == 0) g_cnt[r] = cnt;
}

// ---- prep 1b: share width across each group of 4 consecutive rows --------
__global__ void k_group() {
    int g = blockIdx.x * blockDim.x + threadIdx.x;     // group id, N/4 groups
    if (g >= N / 4) return;
    int m = g_cnt[4 * g];
    #pragma unroll
    for (int r = 1; r < 4; r++) {
        int v = g_cnt[4 * g + r];
        m = v > m ? v : m;
    }
    m = (m + 3) & ~3;                                  // pad to multiple of 4
    #pragma unroll
    for (int r = 0; r < 4; r++) g_wpad[4 * g + r] = m;
}

// ---- prep 2: exclusive prefix scan of g_wpad (1 block) -------------------
__global__ void k_scan() {
    __shared__ int sc[1024];
    int i = threadIdx.x;
    int a0 = g_wpad[4 * i + 0];
    int a1 = g_wpad[4 * i + 1];
    int a2 = g_wpad[4 * i + 2];
    int a3 = g_wpad[4 * i + 3];
    int s  = a0 + a1 + a2 + a3;
    sc[i] = s;
    __syncthreads();
    for (int d = 1; d < 1024; d <<= 1) {
        int v   = sc[i];
        int add = (i >= d) ? sc[i - d] : 0;
        __syncthreads();
        sc[i] = v + add;
        __syncthreads();
    }
    int excl = sc[i] - s;
    g_off[4 * i + 0] = excl;
    g_off[4 * i + 1] = excl + a0;
    g_off[4 * i + 2] = excl + a0 + a1;
    g_off[4 * i + 3] = excl + a0 + a1 + a2;
    if (i == 1023) g_off[N] = sc[1023];
}

// ---- prep 3: fill bank-sliced ELL with packed words (1 warp per row) -----
// Element (i, lane) of a row with base b lives at word
//   b*32 + (i>>2)*128 + lane*4 + (i&3).
// Packed word = (round_to_7(bits(val))) | j, where col = 32*j + lane.
__global__ void k_fillell(const float* __restrict__ w) {
    int r    = blockIdx.x * 8 + (threadIdx.x >> 5);
    int lane = threadIdx.x & 31;
    if (r >= N) return;
    const float* row = w + (size_t)r * N;
    int b   = g_off[r];
    int wid = g_off[r + 1] - b;
    unsigned* base = g_ell + (size_t)b * 32;
    int i = 0;
    for (int k = 0; k < N / 32; k++) {
        float v = row[k * 32 + lane];
        if (v != 0.0f) {
            unsigned bits = (__float_as_uint(v) + 64u) & ~127u;
            base[(i >> 2) * 128 + lane * 4 + (i & 3)] = bits | (unsigned)k;
            i++;
        }
    }
    for (; i < wid; i++)
        base[(i >> 2) * 128 + lane * 4 + (i & 3)] = 0u;   // padding: 0 * sx[lane]
}

// ---- prep 4: wv scatter, zero output, reset barrier ----------------------
__global__ void k_prep(const float* __restrict__ w_out,
                       const int* __restrict__ mask,
                       float* __restrict__ out, int out_n) {
    int i = blockIdx.x * blockDim.x + threadIdx.x;
    if (i < N)     g_wv[mask[i]] = w_out[i];
    if (i < out_n) out[i] = 0.0f;
    if (i == 0)    g_bar = 0u;
}

// ---------------- main persistent ESN kernel -----------------------------
__global__ void __launch_bounds__(TPB, 1)
k_esn(const float* __restrict__ u, const float* __restrict__ w_in,
      float* __restrict__ out) {
    extern __shared__ unsigned char smem_raw[];
    unsigned* sell = (unsigned*)smem_raw;                 // L_CAP*32 words
    float*    sx   = (float*)(sell + L_CAP * 32);         // N
    int*      lrp  = (int*)(sx + N);                      // RPC+1 (per-lane units)
    float*    wsum = (float*)(lrp + RPC + 1);             // 8

    const int c    = blockIdx.x;
    const int tid  = threadIdx.x;
    const int wid  = tid >> 5;
    const int lane = tid & 31;
    const int row0 = c * RPC;

    const int seg_beg = g_off[row0];
    int seg_pl = g_off[row0 + RPC] - seg_beg;
    if (seg_pl > L_CAP) seg_pl = L_CAP;

    for (int r = tid; r <= RPC; r += TPB) {
        int v = g_off[row0 + r] - seg_beg;
        lrp[r] = v > L_CAP ? L_CAP : v;
    }
    {   // copy ELL segment (16B-aligned: offsets are multiples of 4 per-lane units)
        const uint4* src = (const uint4*)(g_ell + (size_t)seg_beg * 32);
        uint4*       dst = (uint4*)sell;
        int nvec = seg_pl * 8;
        for (int k = tid; k < nvec; k += TPB) dst[k] = src[k];
    }
    for (int j = tid; j < N; j += TPB) sx[j] = 0.0f;
    __syncthreads();

    // per-warp metadata: 4 consecutive rows, one shared width
    const int kb0 = lrp[wid * RPW];
    const int kw  = lrp[wid * RPW + 1] - kb0;            // same for all 4 rows
    float winr[RPW], wvr[RPW];
    #pragma unroll
    for (int rr = 0; rr < RPW; rr++) {
        int gr = row0 + wid * RPW + rr;
        winr[rr] = w_in[gr];
        wvr[rr]  = g_wv[gr];
    }
    const uint4* pbase = (const uint4*)sell + (size_t)kb0 * 8 + lane;
    const int pstride = kw * 8;                          // uint4s between rows

    for (int t = 0; t < T; ++t) {
        const float ut = __ldg(&u[t]);
        float* xout = g_x[t & 1];

        const uint4* p0 = pbase;
        const uint4* p1 = pbase + pstride;
        const uint4* p2 = pbase + 2 * pstride;
        const uint4* p3 = pbase + 3 * pstride;
        float s0 = 0.0f, s1 = 0.0f, s2 = 0.0f, s3 = 0.0f;
        for (int i = 0; i < kw; i += 4) {
            uint4 q0 = *p0; p0 += 32;
            uint4 q1 = *p1; p1 += 32;
            uint4 q2 = *p2; p2 += 32;
            uint4 q3 = *p3; p3 += 32;
            s0 += __uint_as_float(q0.x & 0xFFFFFF80u) * sx[((q0.x & 127u) << 5) + lane];
            s1 += __uint_as_float(q1.x & 0xFFFFFF80u) * sx[((q1.x & 127u) << 5) + lane];
            s2 += __uint_as_float(q2.x & 0xFFFFFF80u) * sx[((q2.x & 127u) << 5) + lane];
            s3 += __uint_as_float(q3.x & 0xFFFFFF80u) * sx[((q3.x & 127u) << 5) + lane];
            s0 += __uint_as_float(q0.y & 0xFFFFFF80u) * sx[((q0.y & 127u) << 5) + lane];
            s1 += __uint_as_float(q1.y & 0xFFFFFF80u) * sx[((q1.y & 127u) << 5) + lane];
            s2 += __uint_as_float(q2.y & 0xFFFFFF80u) * sx[((q2.y & 127u) << 5) + lane];
            s3 += __uint_as_float(q3.y & 0xFFFFFF80u) * sx[((q3.y & 127u) << 5) + lane];
            s0 += __uint_as_float(q0.z & 0xFFFFFF80u) * sx[((q0.z & 127u) << 5) + lane];
            s1 += __uint_as_float(q1.z & 0xFFFFFF80u) * sx[((q1.z & 127u) << 5) + lane];
            s2 += __uint_as_float(q2.z & 0xFFFFFF80u) * sx[((q2.z & 127u) << 5) + lane];
            s3 += __uint_as_float(q3.z & 0xFFFFFF80u) * sx[((q3.z & 127u) << 5) + lane];
            s0 += __uint_as_float(q0.w & 0xFFFFFF80u) * sx[((q0.w & 127u) << 5) + lane];
            s1 += __uint_as_float(q1.w & 0xFFFFFF80u) * sx[((q1.w & 127u) << 5) + lane];
            s2 += __uint_as_float(q2.w & 0xFFFFFF80u) * sx[((q2.w & 127u) << 5) + lane];
            s3 += __uint_as_float(q3.w & 0xFFFFFF80u) * sx[((q3.w & 127u) << 5) + lane];
        }
        // 4 independent butterfly reductions
        #pragma unroll
        for (int o = 16; o; o >>= 1) {
            s0 += __shfl_xor_sync(~0u, s0, o);
            s1 += __shfl_xor_sync(~0u, s1, o);
            s2 += __shfl_xor_sync(~0u, s2, o);
            s3 += __shfl_xor_sync(~0u, s3, o);
        }
        if (lane == 0) {
            float4 xv;
            xv.x = tanhf(winr[0] * ut + s0);
            xv.y = tanhf(winr[1] * ut + s1);
            xv.z = tanhf(winr[2] * ut + s2);
            xv.w = tanhf(winr[3] * ut + s3);
            __stcg((float4*)&xout[row0 + wid * RPW], xv);
            wsum[wid] = wvr[0] * xv.x + wvr[1] * xv.y + wvr[2] * xv.z + wvr[3] * xv.w;
        }
        __syncthreads();   // orders the stcg x-writes before tid0's release below

        if (tid == 0) {
            // release-arrive publishes this CTA's x writes (cumulative release)
            asm volatile("red.release.gpu.global.add.u32 [%0], %1;"
                         :: "l"(&g_bar), "r"(1u) : "memory");
            if (t >= WASH) {          // off-critical-path, overlaps propagation
                float ys = 0.0f;
                #pragma unroll
                for (int w = 0; w < 8; w++) ys += wsum[w];
                atomicAdd(&out[t - WASH], ys);
            }
            unsigned target = (unsigned)(t + 1) * NBLK;
            unsigned v;
            do {
                asm volatile("ld.acquire.gpu.global.u32 %0, [%1];"
                             : "=r"(v) : "l"(&g_bar) : "memory");
            } while (v < target);
        }
        __syncthreads();

        if (t + 1 < T) {
            const float4* xs4 = (const float4*)xout;
            float4*       sx4 = (float4*)sx;
            #pragma unroll
            for (int j = 0; j < 4; j++) {
                int idx = tid + j * TPB;                 // 1024 float4s total
                sx4[idx] = __ldcg(&xs4[idx]);
            }
        }
    }
}

// ---------------- launch ---------------------------------------------------
extern "C" void kernel_launch(void* const* d_in, const int* in_sizes, int n_in,
                              void* d_out, int out_size) {
    const float* u     = (const float*)d_in[0];
    const float* w_res = (const float*)d_in[1];
    const float* w_in  = (const float*)d_in[2];
    const float* w_out = (const float*)d_in[3];
    const int*   mask  = (const int*)d_in[4];
    float*       out   = (float*)d_out;

    const int smem_main = L_CAP * 32 * 4 + N * 4 + (RPC + 1) * 4 + 8 * 4;
    cudaFuncSetAttribute(k_esn, cudaFuncAttributeMaxDynamicSharedMemorySize, smem_main);

    const int rows_grid = (N + 7) / 8;   // 1 warp per row, 8 warps per block
    k_width<<<rows_grid, 256>>>(w_res);
    k_group<<<(N / 4 + 255) / 256, 256>>>();
    k_scan<<<1, 1024>>>();
    k_fillell<<<rows_grid, 256>>>(w_res);
    k_prep<<<(N + 255) / 256, 256>>>(w_out, mask, out, out_size);
    k_esn<<<NBLK, TPB, smem_main>>>(u, w_in, out);
}

// round 7
// speedup vs baseline: 3.7571x; 1.0412x over previous
#include <cuda_runtime.h>
#include <cuda_bf16.h>
#include <math.h>

#define N        4096
#define T        4096
#define WASH     200
#define NBLK     128
#define TPB      512                 // 16 warps -> 4 per SMSP
#define NWARP    (TPB / 32)
#define RPC      (N / NBLK)          // 32 rows per CTA
#define RPW      (RPC / NWARP)       // 2 rows per warp (one group shares width)
#define L_CAP    1472                // per-CTA per-lane ELL word capacity
#define ELL_CAP  6291456             // global ELL words

// ---------------- device globals (no allocations allowed) ----------------
__device__ int      g_cnt[N];         // per-row raw max-lane count
__device__ int      g_wpad[N];        // per-row width, group-shared, mult of 4
__device__ int      g_off[N + 1];     // exclusive prefix of g_wpad (per-lane units)
__device__ unsigned g_ell[ELL_CAP];   // packed (val & ~127) | j words, interleaved-4
__device__ float    g_x[2][N];
__device__ float    g_wv[N];          // wv[mask[i]] = w_out[i]
__device__ unsigned g_bar;            // monotonic barrier counter (reset each launch)

// ---- prep 1: per-row max per-lane nonzero count (1 warp per row) ---------
__global__ void k_width(const float* __restrict__ w) {
    int r    = blockIdx.x * 8 + (threadIdx.x >> 5);
    int lane = threadIdx.x & 31;
    if (r >= N) return;
    const float* row = w + (size_t)r * N;
    int cnt = 0;
    #pragma unroll 8
    for (int k = 0; k < N / 32; k++) cnt += (row[k * 32 + lane] != 0.0f);
    for (int o = 16; o; o >>= 1) {
        int v = __shfl_xor_sync(~0u, cnt, o);
        cnt = v > cnt ? v : cnt;
    }
    if (lane == 0) g_cnt[r] = cnt;
}

// ---- prep 1b: share width across each group of RPW consecutive rows ------
__global__ void k_group() {
    int g = blockIdx.x * blockDim.x + threadIdx.x;     // group id, N/RPW groups
    if (g >= N / RPW) return;
    int m = g_cnt[RPW * g];
    #pragma unroll
    for (int r = 1; r < RPW; r++) {
        int v = g_cnt[RPW * g + r];
        m = v > m ? v : m;
    }
    m = (m + 3) & ~3;                                  // pad to multiple of 4
    #pragma unroll
    for (int r = 0; r < RPW; r++) g_wpad[RPW * g + r] = m;
}

// ---- prep 2: exclusive prefix scan of g_wpad (1 block) -------------------
__global__ void k_scan() {
    __shared__ int sc[1024];
    int i = threadIdx.x;
    int a0 = g_wpad[4 * i + 0];
    int a1 = g_wpad[4 * i + 1];
    int a2 = g_wpad[4 * i + 2];
    int a3 = g_wpad[4 * i + 3];
    int s  = a0 + a1 + a2 + a3;
    sc[i] = s;
    __syncthreads();
    for (int d = 1; d < 1024; d <<= 1) {
        int v   = sc[i];
        int add = (i >= d) ? sc[i - d] : 0;
        __syncthreads();
        sc[i] = v + add;
        __syncthreads();
    }
    int excl = sc[i] - s;
    g_off[4 * i + 0] = excl;
    g_off[4 * i + 1] = excl + a0;
    g_off[4 * i + 2] = excl + a0 + a1;
    g_off[4 * i + 3] = excl + a0 + a1 + a2;
    if (i == 1023) g_off[N] = sc[1023];
}

// ---- prep 3: fill bank-sliced ELL with packed words (1 warp per row) -----
// Element (i, lane) of a row with base b lives at word
//   b*32 + (i>>2)*128 + lane*4 + (i&3).
// Packed word = (round_to_7(bits(val))) | j, where col = 32*j + lane.
__global__ void k_fillell(const float* __restrict__ w) {
    int r    = blockIdx.x * 8 + (threadIdx.x >> 5);
    int lane = threadIdx.x & 31;
    if (r >= N) return;
    const float* row = w + (size_t)r * N;
    int b   = g_off[r];
    int wid = g_off[r + 1] - b;
    unsigned* base = g_ell + (size_t)b * 32;
    int i = 0;
    for (int k = 0; k < N / 32; k++) {
        float v = row[k * 32 + lane];
        if (v != 0.0f) {
            unsigned bits = (__float_as_uint(v) + 64u) & ~127u;
            base[(i >> 2) * 128 + lane * 4 + (i & 3)] = bits | (unsigned)k;
            i++;
        }
    }
    for (; i < wid; i++)
        base[(i >> 2) * 128 + lane * 4 + (i & 3)] = 0u;   // padding: 0 * sx[lane]
}

// ---- prep 4: wv scatter, zero output, reset barrier ----------------------
__global__ void k_prep(const float* __restrict__ w_out,
                       const int* __restrict__ mask,
                       float* __restrict__ out, int out_n) {
    int i = blockIdx.x * blockDim.x + threadIdx.x;
    if (i < N)     g_wv[mask[i]] = w_out[i];
    if (i < out_n) out[i] = 0.0f;
    if (i == 0)    g_bar = 0u;
}

// ---------------- main persistent ESN kernel -----------------------------
__global__ void __launch_bounds__(TPB, 1)
k_esn(const float* __restrict__ u, const float* __restrict__ w_in,
      float* __restrict__ out) {
    extern __shared__ unsigned char smem_raw[];
    unsigned* sell = (unsigned*)smem_raw;                 // L_CAP*32 words
    float*    sx   = (float*)(sell + L_CAP * 32);         // N
    int*      lrp  = (int*)(sx + N);                      // RPC+1 (per-lane units)
    float*    wsum = (float*)(lrp + RPC + 1);             // NWARP

    const int c    = blockIdx.x;
    const int tid  = threadIdx.x;
    const int wid  = tid >> 5;
    const int lane = tid & 31;
    const int row0 = c * RPC;

    const int seg_beg = g_off[row0];
    int seg_pl = g_off[row0 + RPC] - seg_beg;
    if (seg_pl > L_CAP) seg_pl = L_CAP;

    for (int r = tid; r <= RPC; r += TPB) {
        int v = g_off[row0 + r] - seg_beg;
        lrp[r] = v > L_CAP ? L_CAP : v;
    }
    {   // copy ELL segment (16B-aligned: offsets are multiples of 4 per-lane units)
        const uint4* src = (const uint4*)(g_ell + (size_t)seg_beg * 32);
        uint4*       dst = (uint4*)sell;
        int nvec = seg_pl * 8;
        for (int k = tid; k < nvec; k += TPB) dst[k] = src[k];
    }
    for (int j = tid; j < N; j += TPB) sx[j] = 0.0f;
    __syncthreads();

    // per-warp metadata: RPW consecutive rows, one shared width
    const int kb0 = lrp[wid * RPW];
    const int kw  = lrp[wid * RPW + 1] - kb0;            // same for both rows
    float winr[RPW], wvr[RPW];
    #pragma unroll
    for (int rr = 0; rr < RPW; rr++) {
        int gr = row0 + wid * RPW + rr;
        winr[rr] = w_in[gr];
        wvr[rr]  = g_wv[gr];
    }
    const uint4* pbase = (const uint4*)sell + (size_t)kb0 * 8 + lane;
    const int pstride = kw * 8;                          // uint4s between rows

    for (int t = 0; t < T; ++t) {
        const float ut = __ldg(&u[t]);
        float* xout = g_x[t & 1];

        const uint4* p0 = pbase;
        const uint4* p1 = pbase + pstride;
        float s0 = 0.0f, s1 = 0.0f;
        for (int i = 0; i < kw; i += 4) {
            uint4 q0 = *p0; p0 += 32;
            uint4 q1 = *p1; p1 += 32;
            s0 += __uint_as_float(q0.x & 0xFFFFFF80u) * sx[((q0.x & 127u) << 5) + lane];
            s1 += __uint_as_float(q1.x & 0xFFFFFF80u) * sx[((q1.x & 127u) << 5) + lane];
            s0 += __uint_as_float(q0.y & 0xFFFFFF80u) * sx[((q0.y & 127u) << 5) + lane];
            s1 += __uint_as_float(q1.y & 0xFFFFFF80u) * sx[((q1.y & 127u) << 5) + lane];
            s0 += __uint_as_float(q0.z & 0xFFFFFF80u) * sx[((q0.z & 127u) << 5) + lane];
            s1 += __uint_as_float(q1.z & 0xFFFFFF80u) * sx[((q1.z & 127u) << 5) + lane];
            s0 += __uint_as_float(q0.w & 0xFFFFFF80u) * sx[((q0.w & 127u) << 5) + lane];
            s1 += __uint_as_float(q1.w & 0xFFFFFF80u) * sx[((q1.w & 127u) << 5) + lane];
        }
        // 2 independent butterfly reductions
        #pragma unroll
        for (int o = 16; o; o >>= 1) {
            s0 += __shfl_xor_sync(~0u, s0, o);
            s1 += __shfl_xor_sync(~0u, s1, o);
        }
        if (lane == 0) {
            float2 xv;
            xv.x = tanhf(winr[0] * ut + s0);
            xv.y = tanhf(winr[1] * ut + s1);
            __stcg((float2*)&xout[row0 + wid * RPW], xv);
            wsum[wid] = wvr[0] * xv.x + wvr[1] * xv.y;
        }
        __syncthreads();   // orders the stcg x-writes before tid0's release below

        if (tid == 0) {
            // release-arrive publishes this CTA's x writes (cumulative release)
            asm volatile("red.release.gpu.global.add.u32 [%0], %1;"
                         :: "l"(&g_bar), "r"(1u) : "memory");
            if (t >= WASH) {          // off-critical-path, overlaps propagation
                float ys = 0.0f;
                #pragma unroll
                for (int w = 0; w < NWARP; w++) ys += wsum[w];
                atomicAdd(&out[t - WASH], ys);
            }
            unsigned target = (unsigned)(t + 1) * NBLK;
            unsigned v;
            do {
                asm volatile("ld.acquire.gpu.global.u32 %0, [%1];"
                             : "=r"(v) : "l"(&g_bar) : "memory");
            } while (v < target);
        }
        __syncthreads();

        if (t + 1 < T) {
            const float4* xs4 = (const float4*)xout;
            float4*       sx4 = (float4*)sx;
            #pragma unroll
            for (int j = 0; j < 2; j++) {
                int idx = tid + j * TPB;                 // 1024 float4s total
                sx4[idx] = __ldcg(&xs4[idx]);
            }
        }
        __syncthreads();   // RACE FIX: sx reload must complete before next
                           // iteration's gathers read sx (was the round-6 bug,
                           // latent in every earlier round)
    }
}

// ---------------- launch ---------------------------------------------------
extern "C" void kernel_launch(void* const* d_in, const int* in_sizes, int n_in,
                              void* d_out, int out_size) {
    const float* u     = (const float*)d_in[0];
    const float* w_res = (const float*)d_in[1];
    const float* w_in  = (const float*)d_in[2];
    const float* w_out = (const float*)d_in[3];
    const int*   mask  = (const int*)d_in[4];
    float*       out   = (float*)d_out;

    const int smem_main = L_CAP * 32 * 4 + N * 4 + (RPC + 1) * 4 + NWARP * 4;
    cudaFuncSetAttribute(k_esn, cudaFuncAttributeMaxDynamicSharedMemorySize, smem_main);

    const int rows_grid = (N + 7) / 8;   // 1 warp per row, 8 warps per block
    k_width<<<rows_grid, 256>>>(w_res);
    k_group<<<(N / RPW + 255) / 256, 256>>>();
    k_scan<<<1, 1024>>>();
    k_fillell<<<rows_grid, 256>>>(w_res);
    k_prep<<<(N + 255) / 256, 256>>>(w_out, mask, out, out_size);
    k_esn<<<NBLK, TPB, smem_main>>>(u, w_in, out);
}

// round 8
// speedup vs baseline: 3.7861x; 1.0077x over previous
#include <cuda_runtime.h>
#include <cuda_bf16.h>
#include <math.h>

#define N        4096
#define T        4096
#define WASH     200
#define NBLK     128
#define TPB      1024                // 32 warps -> 8 per SMSP
#define NWARP    (TPB / 32)
#define RPC      (N / NBLK)          // 32 rows per CTA
#define RPW      (RPC / NWARP)       // 1 row per warp
#define L_CAP    1472                // per-CTA per-lane ELL word capacity
#define ELL_CAP  6291456             // global ELL words

// ---------------- device globals (no allocations allowed) ----------------
__device__ int      g_cnt[N];         // per-row raw max-lane count
__device__ int      g_wpad[N];        // per-row padded width (mult of 4)
__device__ int      g_off[N + 1];     // exclusive prefix of g_wpad (per-lane units)
__device__ unsigned g_ell[ELL_CAP];   // packed (val & ~127) | j words, interleaved-4
__device__ float    g_x[2][N];
__device__ float    g_wv[N];          // wv[mask[i]] = w_out[i]
__device__ unsigned g_bar;            // monotonic barrier counter (reset each launch)

// ---- prep 1: per-row max per-lane nonzero count (1 warp per row) ---------
__global__ void k_width(const float* __restrict__ w) {
    int r    = blockIdx.x * 8 + (threadIdx.x >> 5);
    int lane = threadIdx.x & 31;
    if (r >= N) return;
    const float* row = w + (size_t)r * N;
    int cnt = 0;
    #pragma unroll 8
    for (int k = 0; k < N / 32; k++) cnt += (row[k * 32 + lane] != 0.0f);
    for (int o = 16; o; o >>= 1) {
        int v = __shfl_xor_sync(~0u, cnt, o);
        cnt = v > cnt ? v : cnt;
    }
    if (lane == 0) g_cnt[r] = cnt;
}

// ---- prep 1b: pad each row's width to a multiple of 4 (RPW=1: no group) --
__global__ void k_group() {
    int g = blockIdx.x * blockDim.x + threadIdx.x;
    if (g >= N) return;
    g_wpad[g] = (g_cnt[g] + 3) & ~3;
}

// ---- prep 2: exclusive prefix scan of g_wpad (1 block) -------------------
__global__ void k_scan() {
    __shared__ int sc[1024];
    int i = threadIdx.x;
    int a0 = g_wpad[4 * i + 0];
    int a1 = g_wpad[4 * i + 1];
    int a2 = g_wpad[4 * i + 2];
    int a3 = g_wpad[4 * i + 3];
    int s  = a0 + a1 + a2 + a3;
    sc[i] = s;
    __syncthreads();
    for (int d = 1; d < 1024; d <<= 1) {
        int v   = sc[i];
        int add = (i >= d) ? sc[i - d] : 0;
        __syncthreads();
        sc[i] = v + add;
        __syncthreads();
    }
    int excl = sc[i] - s;
    g_off[4 * i + 0] = excl;
    g_off[4 * i + 1] = excl + a0;
    g_off[4 * i + 2] = excl + a0 + a1;
    g_off[4 * i + 3] = excl + a0 + a1 + a2;
    if (i == 1023) g_off[N] = sc[1023];
}

// ---- prep 3: fill bank-sliced ELL with packed words (1 warp per row) -----
// Element (i, lane) of a row with base b lives at word
//   b*32 + (i>>2)*128 + lane*4 + (i&3).
// Packed word = (round_to_7(bits(val))) | j, where col = 32*j + lane.
__global__ void k_fillell(const float* __restrict__ w) {
    int r    = blockIdx.x * 8 + (threadIdx.x >> 5);
    int lane = threadIdx.x & 31;
    if (r >= N) return;
    const float* row = w + (size_t)r * N;
    int b   = g_off[r];
    int wid = g_off[r + 1] - b;
    unsigned* base = g_ell + (size_t)b * 32;
    int i = 0;
    for (int k = 0; k < N / 32; k++) {
        float v = row[k * 32 + lane];
        if (v != 0.0f) {
            unsigned bits = (__float_as_uint(v) + 64u) & ~127u;
            base[(i >> 2) * 128 + lane * 4 + (i & 3)] = bits | (unsigned)k;
            i++;
        }
    }
    for (; i < wid; i++)
        base[(i >> 2) * 128 + lane * 4 + (i & 3)] = 0u;   // padding: 0 * sx[lane]
}

// ---- prep 4: wv scatter, zero output, reset barrier ----------------------
__global__ void k_prep(const float* __restrict__ w_out,
                       const int* __restrict__ mask,
                       float* __restrict__ out, int out_n) {
    int i = blockIdx.x * blockDim.x + threadIdx.x;
    if (i < N)     g_wv[mask[i]] = w_out[i];
    if (i < out_n) out[i] = 0.0f;
    if (i == 0)    g_bar = 0u;
}

// ---------------- main persistent ESN kernel -----------------------------
__global__ void __launch_bounds__(TPB, 1)
k_esn(const float* __restrict__ u, const float* __restrict__ w_in,
      float* __restrict__ out) {
    extern __shared__ unsigned char smem_raw[];
    unsigned* sell = (unsigned*)smem_raw;                 // L_CAP*32 words
    float*    sx   = (float*)(sell + L_CAP * 32);         // N
    int*      lrp  = (int*)(sx + N);                      // RPC+1 (per-lane units)
    float*    wsum = (float*)(lrp + RPC + 1);             // NWARP

    const int c    = blockIdx.x;
    const int tid  = threadIdx.x;
    const int wid  = tid >> 5;
    const int lane = tid & 31;
    const int row0 = c * RPC;

    const int seg_beg = g_off[row0];
    int seg_pl = g_off[row0 + RPC] - seg_beg;
    if (seg_pl > L_CAP) seg_pl = L_CAP;

    for (int r = tid; r <= RPC; r += TPB) {
        int v = g_off[row0 + r] - seg_beg;
        lrp[r] = v > L_CAP ? L_CAP : v;
    }
    {   // copy ELL segment (16B-aligned: offsets are multiples of 4 per-lane units)
        const uint4* src = (const uint4*)(g_ell + (size_t)seg_beg * 32);
        uint4*       dst = (uint4*)sell;
        int nvec = seg_pl * 8;
        for (int k = tid; k < nvec; k += TPB) dst[k] = src[k];
    }
    for (int j = tid; j < N; j += TPB) sx[j] = 0.0f;
    __syncthreads();

    // per-warp metadata: one row per warp
    const int kb0 = lrp[wid];
    const int kw  = lrp[wid + 1] - kb0;
    const int gr  = row0 + wid;
    const float winr = w_in[gr];
    const float wvr  = g_wv[gr];
    const uint4* pbase = (const uint4*)sell + (size_t)kb0 * 8 + lane;

    for (int t = 0; t < T; ++t) {
        const float ut = __ldg(&u[t]);
        float* xout = g_x[t & 1];

        const uint4* p0 = pbase;
        float s0 = 0.0f;
        for (int i = 0; i < kw; i += 4) {
            uint4 q0 = *p0; p0 += 32;
            s0 += __uint_as_float(q0.x & 0xFFFFFF80u) * sx[((q0.x & 127u) << 5) + lane];
            s0 += __uint_as_float(q0.y & 0xFFFFFF80u) * sx[((q0.y & 127u) << 5) + lane];
            s0 += __uint_as_float(q0.z & 0xFFFFFF80u) * sx[((q0.z & 127u) << 5) + lane];
            s0 += __uint_as_float(q0.w & 0xFFFFFF80u) * sx[((q0.w & 127u) << 5) + lane];
        }
        #pragma unroll
        for (int o = 16; o; o >>= 1)
            s0 += __shfl_xor_sync(~0u, s0, o);
        if (lane == 0) {
            float xv = tanhf(winr * ut + s0);
            __stcg(&xout[gr], xv);
            wsum[wid] = wvr * xv;
        }
        __syncthreads();   // orders the stcg x-writes before tid0's release below

        if (tid == 0) {
            // release-arrive publishes this CTA's x writes (cumulative release)
            asm volatile("red.release.gpu.global.add.u32 [%0], %1;"
                         :: "l"(&g_bar), "r"(1u) : "memory");
            if (t >= WASH) {          // off-critical-path, overlaps propagation
                float ys = 0.0f;
                #pragma unroll
                for (int w = 0; w < NWARP; w++) ys += wsum[w];
                atomicAdd(&out[t - WASH], ys);
            }
            unsigned target = (unsigned)(t + 1) * NBLK;
            unsigned v;
            do {
                asm volatile("ld.acquire.gpu.global.u32 %0, [%1];"
                             : "=r"(v) : "l"(&g_bar) : "memory");
            } while (v < target);
        }
        __syncthreads();

        if (t + 1 < T) {
            const float4* xs4 = (const float4*)xout;
            float4*       sx4 = (float4*)sx;
            sx4[tid] = __ldcg(&xs4[tid]);                // 1024 float4s total
        }
        __syncthreads();   // RACE FIX: sx reload must complete before next
                           // iteration's gathers read sx
    }
}

// ---------------- launch ---------------------------------------------------
extern "C" void kernel_launch(void* const* d_in, const int* in_sizes, int n_in,
                              void* d_out, int out_size) {
    const float* u     = (const float*)d_in[0];
    const float* w_res = (const float*)d_in[1];
    const float* w_in  = (const float*)d_in[2];
    const float* w_out = (const float*)d_in[3];
    const int*   mask  = (const int*)d_in[4];
    float*       out   = (float*)d_out;

    const int smem_main = L_CAP * 32 * 4 + N * 4 + (RPC + 1) * 4 + NWARP * 4;
    cudaFuncSetAttribute(k_esn, cudaFuncAttributeMaxDynamicSharedMemorySize, smem_main);

    const int rows_grid = (N + 7) / 8;   // 1 warp per row, 8 warps per block
    k_width<<<rows_grid, 256>>>(w_res);
    k_group<<<(N + 255) / 256, 256>>>();
    k_scan<<<1, 1024>>>();
    k_fillell<<<rows_grid, 256>>>(w_res);
    k_prep<<<(N + 255) / 256, 256>>>(w_out, mask, out, out_size);
    k_esn<<<NBLK, TPB, smem_main>>>(u, w_in, out);
}